// round 12
// baseline (speedup 1.0000x reference)
#include <cuda_runtime.h>
#include <cuda_bf16.h>
#include <cstdint>

#define B_   2
#define T_   2048
#define C_   768
#define H_   12
#define DH_  64
#define M_   (B_ * T_)        // 4096 token rows
#define N3C_ (3 * C_)         // 2304

// ---------------------------------------------------------------------------
// Scratch (allocation-free rule: device globals) — all split hi/lo bf16
// ---------------------------------------------------------------------------
__device__ __nv_bfloat16 g_xh[M_ * C_],     g_xl[M_ * C_];      // x split
__device__ __nv_bfloat16 g_wqT_h[N3C_ * C_], g_wqT_l[N3C_ * C_]; // Wqkv^T split
__device__ __nv_bfloat16 g_woT_h[C_ * C_],  g_woT_l[C_ * C_];   // Wout^T split
__device__ __nv_bfloat16 g_qkvh[M_ * N3C_], g_qkvl[M_ * N3C_];  // qkv split
__device__ __nv_bfloat16 g_atth[M_ * C_],   g_attl[M_ * C_];    // att out split

// ---------------------------------------------------------------------------
// Helpers
// ---------------------------------------------------------------------------
__device__ __forceinline__ void split2(float x, float y, uint32_t& hi, uint32_t& lo)
{
    __nv_bfloat16 hx = __float2bfloat16_rn(x);
    __nv_bfloat16 hy = __float2bfloat16_rn(y);
    float rx = x - __bfloat162float(hx);
    float ry = y - __bfloat162float(hy);
    __nv_bfloat162 H; H.x = hx; H.y = hy;
    __nv_bfloat162 L = __floats2bfloat162_rn(rx, ry);
    hi = *reinterpret_cast<uint32_t*>(&H);
    lo = *reinterpret_cast<uint32_t*>(&L);
}

__device__ __forceinline__ void lm4(uint32_t* r, uint32_t addr)
{
    asm volatile("ldmatrix.sync.aligned.m8n8.x4.shared.b16 {%0,%1,%2,%3}, [%4];"
                 : "=r"(r[0]), "=r"(r[1]), "=r"(r[2]), "=r"(r[3]) : "r"(addr));
}

__device__ __forceinline__ void lm4t(uint32_t* r, uint32_t addr)
{
    asm volatile("ldmatrix.sync.aligned.m8n8.x4.trans.shared.b16 {%0,%1,%2,%3}, [%4];"
                 : "=r"(r[0]), "=r"(r[1]), "=r"(r[2]), "=r"(r[3]) : "r"(addr));
}

__device__ __forceinline__ void mma16816(float* d, const uint32_t* a,
                                         uint32_t b0, uint32_t b1)
{
    asm volatile("mma.sync.aligned.m16n8k16.row.col.f32.bf16.bf16.f32 "
                 "{%0,%1,%2,%3}, {%4,%5,%6,%7}, {%8,%9}, {%0,%1,%2,%3};"
                 : "+f"(d[0]), "+f"(d[1]), "+f"(d[2]), "+f"(d[3])
                 : "r"(a[0]), "r"(a[1]), "r"(a[2]), "r"(a[3]), "r"(b0), "r"(b1));
}

__device__ __forceinline__ void cpa16(uint32_t dst, const void* src)
{
    asm volatile("cp.async.cg.shared.global [%0], [%1], 16;" :: "r"(dst), "l"(src));
}
__device__ __forceinline__ void cp_commit()
{
    asm volatile("cp.async.commit_group;");
}
__device__ __forceinline__ void cp_wait0()
{
    asm volatile("cp.async.wait_group 0;");
}
__device__ __forceinline__ void cp_wait1()
{
    asm volatile("cp.async.wait_group 1;");
}

// ---------------------------------------------------------------------------
// One-shot converters
// ---------------------------------------------------------------------------
__global__ void split_flat_kernel(const float* __restrict__ src,
                                  __nv_bfloat16* __restrict__ hi,
                                  __nv_bfloat16* __restrict__ lo, int n4)
{
    int i = blockIdx.x * blockDim.x + threadIdx.x;
    if (i >= n4) return;
    float4 v = ((const float4*)src)[i];
    uint32_t h0, l0, h1, l1;
    split2(v.x, v.y, h0, l0);
    split2(v.z, v.w, h1, l1);
    ((uint2*)hi)[i] = make_uint2(h0, h1);
    ((uint2*)lo)[i] = make_uint2(l0, l1);
}

// src [R][N] fp32 -> dst [N][R] hi/lo bf16  (R,N multiples of 32)
__global__ void splitT_kernel(const float* __restrict__ src,
                              __nv_bfloat16* __restrict__ hiT,
                              __nv_bfloat16* __restrict__ loT,
                              int R, int N)
{
    __shared__ float t[32][33];
    const int c0 = blockIdx.x * 32, r0 = blockIdx.y * 32;
    const int tx = threadIdx.x, ty = threadIdx.y;   // (32,8)
    #pragma unroll
    for (int j = 0; j < 4; j++)
        t[ty + j * 8][tx] = src[(size_t)(r0 + ty + j * 8) * N + c0 + tx];
    __syncthreads();
    #pragma unroll
    for (int j = 0; j < 4; j++) {
        float v = t[tx][ty + j * 8];
        __nv_bfloat16 h = __float2bfloat16_rn(v);
        float r = v - __bfloat162float(h);
        size_t o = (size_t)(c0 + ty + j * 8) * R + r0 + tx;
        hiT[o] = h;
        loT[o] = __float2bfloat16_rn(r);
    }
}

// ---------------------------------------------------------------------------
// Pre-split bf16 GEMM: C[M,N] = (Ah+Al)[M,K] @ (Bh+Bl)^T  (B given as [N][K]).
// Block 128x128, BK=32, 3-stage cp.async pipeline (96KB smem, 2 CTAs/SM).
// 64B smem rows, swizzle s = c ^ ((m>>1)&3)  (conflict-free ldmatrix phases).
// ---------------------------------------------------------------------------
#define GEMM_STAGE 32768
#define GEMM_SMEM  (3 * GEMM_STAGE)

template<bool SPLIT_OUT>
__global__ __launch_bounds__(256, 2)
void gemm_pre_kernel(const __nv_bfloat16* __restrict__ Ah,
                     const __nv_bfloat16* __restrict__ Al,
                     const __nv_bfloat16* __restrict__ Bh,
                     const __nv_bfloat16* __restrict__ Bl,
                     float* __restrict__ C,
                     __nv_bfloat16* __restrict__ Ch,
                     __nv_bfloat16* __restrict__ Cl,
                     int M, int N, int K)
{
    extern __shared__ uint8_t smraw[];
    const uint32_t sb = (uint32_t)__cvta_generic_to_shared(smraw);

    const int tid  = threadIdx.x;
    const int lane = tid & 31;
    const int warp = tid >> 5;
    const int wr   = warp >> 2;
    const int wc   = warp & 3;
    const int row0 = blockIdx.y * 128;
    const int col0 = blockIdx.x * 128;

    const int l7    = lane & 7;
    const int a_row = wr * 64 + (lane & 15);
    const int a_chi = lane >> 4;
    const int b_n   = wc * 32 + ((lane >> 4) << 3) + l7;
    const int b_ckb = (lane >> 3) & 1;

    // loader coords: each thread stores 2 chunks of 16B per array
    const int lm = tid >> 1;            // row 0..127
    const int lbc = (tid & 1) * 2;      // chunk base 0 or 2

    float acc[4][4][4];
    #pragma unroll
    for (int i = 0; i < 4; i++)
        #pragma unroll
        for (int j = 0; j < 4; j++)
            #pragma unroll
            for (int r = 0; r < 4; r++) acc[i][j][r] = 0.f;

    const int nk = K >> 5;   // K/32

    auto issue = [&](int s, int k0) {
        uint32_t base = sb + s * GEMM_STAGE;
        #pragma unroll
        for (int c = 0; c < 2; c++) {
            int ch = lbc + c;
            uint32_t sw = lm * 64 + ((uint32_t)(ch ^ ((lm >> 1) & 3)) << 4);
            const size_t ga = (size_t)(row0 + lm) * K + k0 + ch * 8;
            const size_t gb = (size_t)(col0 + lm) * K + k0 + ch * 8;
            cpa16(base + sw,         Ah + ga);
            cpa16(base + 8192 + sw,  Al + ga);
            cpa16(base + 16384 + sw, Bh + gb);
            cpa16(base + 24576 + sw, Bl + gb);
        }
    };

    issue(0, 0);  cp_commit();
    issue(1, 32); cp_commit();

    for (int k = 0; k < nk; k++) {
        cp_wait1();
        __syncthreads();
        if (k + 2 < nk) issue((k + 2) % 3, (k + 2) * 32);
        cp_commit();

        const uint32_t st = sb + (k % 3) * GEMM_STAGE;
        #pragma unroll
        for (int kk = 0; kk < 2; kk++) {
            uint32_t bh[8], bl[8];
            #pragma unroll
            for (int np = 0; np < 2; np++) {
                int n = b_n + np * 16;
                int bc = 2 * kk + b_ckb;
                uint32_t boff = n * 64 + ((uint32_t)(bc ^ ((n >> 1) & 3)) << 4);
                lm4(&bh[np * 4], st + 16384 + boff);
                lm4(&bl[np * 4], st + 24576 + boff);
            }
            #pragma unroll
            for (int mt = 0; mt < 4; mt++) {
                int row = a_row + mt * 16;
                int ac = 2 * kk + a_chi;
                uint32_t aoff = row * 64 + ((uint32_t)(ac ^ ((row >> 1) & 3)) << 4);
                uint32_t ah[4], al[4];
                lm4(ah, st + aoff);
                lm4(al, st + 8192 + aoff);
                #pragma unroll
                for (int nt = 0; nt < 4; nt++) {
                    int bi = (nt >> 1) * 4 + (nt & 1) * 2;
                    mma16816(acc[mt][nt], ah, bh[bi], bh[bi + 1]);
                    mma16816(acc[mt][nt], ah, bl[bi], bl[bi + 1]);
                    mma16816(acc[mt][nt], al, bh[bi], bh[bi + 1]);
                }
            }
        }
    }

    const int g  = lane >> 2;
    const int tg = lane & 3;
    #pragma unroll
    for (int mt = 0; mt < 4; mt++) {
        #pragma unroll
        for (int nt = 0; nt < 4; nt++) {
            int r = row0 + wr * 64 + mt * 16 + g;
            int c = col0 + wc * 32 + nt * 8 + tg * 2;
            if (SPLIT_OUT) {
                uint32_t hh, ll;
                split2(acc[mt][nt][0], acc[mt][nt][1], hh, ll);
                *(uint32_t*)&Ch[(size_t)r * N + c] = hh;
                *(uint32_t*)&Cl[(size_t)r * N + c] = ll;
                split2(acc[mt][nt][2], acc[mt][nt][3], hh, ll);
                *(uint32_t*)&Ch[(size_t)(r + 8) * N + c] = hh;
                *(uint32_t*)&Cl[(size_t)(r + 8) * N + c] = ll;
            } else {
                *(float2*)&C[(size_t)r * N + c] =
                    make_float2(acc[mt][nt][0], acc[mt][nt][1]);
                *(float2*)&C[(size_t)(r + 8) * N + c] =
                    make_float2(acc[mt][nt][2], acc[mt][nt][3]);
            }
        }
    }
}

// ---------------------------------------------------------------------------
// Tensor-core flash attention (causal), split-bf16, pre-split inputs.
// Block: 128 Q-rows x 64 K-cols, 8 warps. cp.async double-buffered K/V.
// Q fragments hoisted to registers after prologue.
// Smem 96KB: Qh@0 Ql@16K (128x64); KV buf0@32K, buf1@64K
//            (each: Kh +0, Kl +8K, Vh +16K, Vl +24K; 64x64 tiles).
// ---------------------------------------------------------------------------
#define FBM 128
#define FBN 64
#define FLASH_TC_SMEM (96 * 1024)

__global__ __launch_bounds__(256)
void flash_tc_kernel()
{
    extern __shared__ uint8_t fsm[];
    const uint32_t sb  = (uint32_t)__cvta_generic_to_shared(fsm);
    const uint32_t sQhi = sb;
    const uint32_t sQlo = sb + 16384;

    const int tid  = threadIdx.x;
    const int lane = tid & 31;
    const int w    = tid >> 5;
    const int g    = lane >> 2;
    const int tg   = lane & 3;
    const int bh   = blockIdx.y;
    const int b    = bh / H_;
    const int h    = bh % H_;
    const int qt   = (T_ / FBM - 1) - blockIdx.x;   // heavy q-blocks first
    const int q0   = qt * FBM;
    const long rowbase = (long)b * T_;
    const int qoff = h * DH_;
    const int koff = C_ + h * DH_;
    const int voff = 2 * C_ + h * DH_;
    const float scale = 0.125f;

    auto issueKV = [&](int buf, int k0) {
        const uint32_t kvb = sb + 32768 + buf * 32768;
        #pragma unroll
        for (int i = 0; i < 8; i++) {
            int idx   = tid + i * 256;
            int tsel  = idx >> 9;            // 0:Kh 1:Kl 2:Vh 3:Vl
            int local = idx & 511;
            int m = local >> 3, ch = local & 7;
            const __nv_bfloat16* src = (tsel & 1) ? g_qkvl : g_qkvh;
            int off_ = (tsel < 2) ? koff : voff;
            cpa16(kvb + tsel * 8192 + m * 128 + (((ch ^ (m & 7))) << 4),
                  &src[(rowbase + k0 + m) * (size_t)N3C_ + off_ + ch * 8]);
        }
    };

    // ---- load Q tile [128][64] hi/lo into smem (swizzled) ----
    #pragma unroll
    for (int i = 0; i < 8; i++) {
        int idx   = tid + i * 256;
        int tsel  = idx >> 10;            // 0=hi, 1=lo
        int local = idx & 1023;
        int m = local >> 3, ch = local & 7;
        const __nv_bfloat16* src = tsel ? g_qkvl : g_qkvh;
        uint4 v = *(const uint4*)&src[(rowbase + q0 + m) * (size_t)N3C_ + qoff + ch * 8];
        *(uint4*)(fsm + tsel * 16384 + m * 128 + (((ch ^ (m & 7))) << 4)) = v;
    }

    issueKV(0, 0);
    cp_commit();

    __syncthreads();   // Q smem visible to all warps

    // ---- hoist Q fragments (loop-invariant) into registers ----
    const int wrow0 = q0 + w * 16;
    const int arow  = w * 16 + (lane & 15);
    uint32_t qah[4][4], qal[4][4];
    #pragma unroll
    for (int kk = 0; kk < 4; kk++) {
        uint32_t aoff = arow * 128 + (((2 * kk + (lane >> 4)) ^ (arow & 7)) << 4);
        lm4(qah[kk], sQhi + aoff);
        lm4(qal[kk], sQlo + aoff);
    }

    float sacc[8][4], oacc[8][4];
    float mr[2] = {-1e30f, -1e30f};
    float lr[2] = {0.f, 0.f};
    #pragma unroll
    for (int nt = 0; nt < 8; nt++)
        #pragma unroll
        for (int r = 0; r < 4; r++) oacc[nt][r] = 0.f;

    const int nkt = (q0 + FBM) / FBN;

    for (int kt = 0; kt < nkt; kt++) {
        const int k0 = kt * FBN;
        const int cur = kt & 1;
        const bool more = (kt + 1 < nkt);

        if (more) { issueKV(cur ^ 1, k0 + FBN); cp_commit(); }
        if (more) cp_wait1(); else cp_wait0();
        __syncthreads();

        const uint32_t sKhi = sb + 32768 + cur * 32768;
        const uint32_t sKlo = sKhi + 8192;
        const uint32_t sVhi = sKhi + 16384;
        const uint32_t sVlo = sKhi + 24576;

        if (k0 <= wrow0 + 15) {
            // ---- S = Q @ K^T ----
            #pragma unroll
            for (int nt = 0; nt < 8; nt++)
                #pragma unroll
                for (int r = 0; r < 4; r++) sacc[nt][r] = 0.f;

            #pragma unroll
            for (int kk = 0; kk < 4; kk++) {
                #pragma unroll
                for (int ng = 0; ng < 4; ng++) {
                    int n = ng * 16 + ((lane >> 4) << 3) + (lane & 7);
                    uint32_t boff = n * 128 +
                        (((2 * kk + ((lane >> 3) & 1)) ^ (n & 7)) << 4);
                    uint32_t bhv[4], blv[4];
                    lm4(bhv, sKhi + boff);
                    lm4(blv, sKlo + boff);
                    mma16816(sacc[2 * ng],     qah[kk], bhv[0], bhv[1]);
                    mma16816(sacc[2 * ng + 1], qah[kk], bhv[2], bhv[3]);
                    mma16816(sacc[2 * ng],     qah[kk], blv[0], blv[1]);
                    mma16816(sacc[2 * ng + 1], qah[kk], blv[2], blv[3]);
                    mma16816(sacc[2 * ng],     qal[kk], bhv[0], bhv[1]);
                    mma16816(sacc[2 * ng + 1], qal[kk], bhv[2], bhv[3]);
                }
            }

            // ---- scale + causal mask + online softmax ----
            const bool maskt = (k0 + FBN - 1 > wrow0);
            #pragma unroll
            for (int r = 0; r < 2; r++) {
                const int grow_ = wrow0 + g + r * 8;
                float tmax = -1e30f;
                #pragma unroll
                for (int nt = 0; nt < 8; nt++) {
                    float v0 = sacc[nt][r * 2]     * scale;
                    float v1 = sacc[nt][r * 2 + 1] * scale;
                    if (maskt) {
                        int col = k0 + nt * 8 + tg * 2;
                        if (col     > grow_) v0 = -1e30f;
                        if (col + 1 > grow_) v1 = -1e30f;
                    }
                    sacc[nt][r * 2]     = v0;
                    sacc[nt][r * 2 + 1] = v1;
                    tmax = fmaxf(tmax, fmaxf(v0, v1));
                }
                tmax = fmaxf(tmax, __shfl_xor_sync(0xffffffffu, tmax, 1));
                tmax = fmaxf(tmax, __shfl_xor_sync(0xffffffffu, tmax, 2));
                float newm  = fmaxf(mr[r], tmax);
                float alpha = __expf(mr[r] - newm);
                float sum = 0.f;
                #pragma unroll
                for (int nt = 0; nt < 8; nt++) {
                    float e0 = __expf(sacc[nt][r * 2]     - newm);
                    float e1 = __expf(sacc[nt][r * 2 + 1] - newm);
                    sacc[nt][r * 2]     = e0;
                    sacc[nt][r * 2 + 1] = e1;
                    sum += e0 + e1;
                }
                sum += __shfl_xor_sync(0xffffffffu, sum, 1);
                sum += __shfl_xor_sync(0xffffffffu, sum, 2);
                lr[r] = lr[r] * alpha + sum;
                mr[r] = newm;
                #pragma unroll
                for (int nt = 0; nt < 8; nt++) {
                    oacc[nt][r * 2]     *= alpha;
                    oacc[nt][r * 2 + 1] *= alpha;
                }
            }

            // ---- O += P @ V ----
            #pragma unroll
            for (int ks = 0; ks < 4; ks++) {
                uint32_t pah[4], pal[4];
                split2(sacc[2 * ks][0],     sacc[2 * ks][1],     pah[0], pal[0]);
                split2(sacc[2 * ks][2],     sacc[2 * ks][3],     pah[1], pal[1]);
                split2(sacc[2 * ks + 1][0], sacc[2 * ks + 1][1], pah[2], pal[2]);
                split2(sacc[2 * ks + 1][2], sacc[2 * ks + 1][3], pah[3], pal[3]);
                const int krow = ks * 16 + (lane & 15);
                #pragma unroll
                for (int dg = 0; dg < 4; dg++) {
                    int ch = dg * 2 + (lane >> 4);
                    uint32_t vb = krow * 128 + (((ch ^ (krow & 7))) << 4);
                    uint32_t vh[4], vl[4];
                    lm4t(vh, sVhi + vb);
                    lm4t(vl, sVlo + vb);
                    mma16816(oacc[2 * dg],     pah, vh[0], vh[1]);
                    mma16816(oacc[2 * dg + 1], pah, vh[2], vh[3]);
                    mma16816(oacc[2 * dg],     pah, vl[0], vl[1]);
                    mma16816(oacc[2 * dg + 1], pah, vl[2], vl[3]);
                    mma16816(oacc[2 * dg],     pal, vh[0], vh[1]);
                    mma16816(oacc[2 * dg + 1], pal, vh[2], vh[3]);
                }
            }
        }

        __syncthreads();   // all reads done before next issue overwrites buffer
    }

    // ---- normalize + write split att ----
    const float inv0 = 1.f / lr[0];
    const float inv1 = 1.f / lr[1];
    const long r0 = rowbase + wrow0 + g;
    #pragma unroll
    for (int nt = 0; nt < 8; nt++) {
        int c = qoff + nt * 8 + tg * 2;
        uint32_t hh, ll;
        split2(oacc[nt][0] * inv0, oacc[nt][1] * inv0, hh, ll);
        *(uint32_t*)&g_atth[r0 * C_ + c] = hh;
        *(uint32_t*)&g_attl[r0 * C_ + c] = ll;
        split2(oacc[nt][2] * inv1, oacc[nt][3] * inv1, hh, ll);
        *(uint32_t*)&g_atth[(r0 + 8) * C_ + c] = hh;
        *(uint32_t*)&g_attl[(r0 + 8) * C_ + c] = ll;
    }
}

// ---------------------------------------------------------------------------
extern "C" void kernel_launch(void* const* d_in, const int* in_sizes, int n_in,
                              void* d_out, int out_size)
{
    const float* x    = (const float*)d_in[0];
    const float* Wqkv = (const float*)d_in[1];
    const float* Wout = (const float*)d_in[2];
    float* out = (float*)d_out;

    __nv_bfloat16 *xh, *xl, *wqh, *wql, *woh, *wol, *qh, *ql, *ath, *atl;
    cudaGetSymbolAddress((void**)&xh,  g_xh);
    cudaGetSymbolAddress((void**)&xl,  g_xl);
    cudaGetSymbolAddress((void**)&wqh, g_wqT_h);
    cudaGetSymbolAddress((void**)&wql, g_wqT_l);
    cudaGetSymbolAddress((void**)&woh, g_woT_h);
    cudaGetSymbolAddress((void**)&wol, g_woT_l);
    cudaGetSymbolAddress((void**)&qh,  g_qkvh);
    cudaGetSymbolAddress((void**)&ql,  g_qkvl);
    cudaGetSymbolAddress((void**)&ath, g_atth);
    cudaGetSymbolAddress((void**)&atl, g_attl);

    cudaFuncSetAttribute(gemm_pre_kernel<true>,
                         cudaFuncAttributeMaxDynamicSharedMemorySize, GEMM_SMEM);
    cudaFuncSetAttribute(gemm_pre_kernel<false>,
                         cudaFuncAttributeMaxDynamicSharedMemorySize, GEMM_SMEM);
    cudaFuncSetAttribute(flash_tc_kernel,
                         cudaFuncAttributeMaxDynamicSharedMemorySize, FLASH_TC_SMEM);

    dim3 blk(256);

    // 0) pre-split inputs
    split_flat_kernel<<<(M_ * C_ / 4 + 255) / 256, 256>>>(x, xh, xl, M_ * C_ / 4);
    splitT_kernel<<<dim3(N3C_ / 32, C_ / 32), dim3(32, 8)>>>(Wqkv, wqh, wql, C_, N3C_);
    splitT_kernel<<<dim3(C_ / 32, C_ / 32),  dim3(32, 8)>>>(Wout, woh, wol, C_, C_);

    // 1) QKV projection -> split qkv
    gemm_pre_kernel<true><<<dim3(N3C_ / 128, M_ / 128), blk, GEMM_SMEM>>>(
        xh, xl, wqh, wql, nullptr, qh, ql, M_, N3C_, C_);

    // 2) causal flash attention -> split att
    flash_tc_kernel<<<dim3(T_ / FBM, B_ * H_), blk, FLASH_TC_SMEM>>>();

    // 3) output projection -> fp32 out
    gemm_pre_kernel<false><<<dim3(C_ / 128, M_ / 128), blk, GEMM_SMEM>>>(
        ath, atl, woh, wol, out, nullptr, nullptr, M_, C_, C_);
}

// round 14
// speedup vs baseline: 1.1935x; 1.1935x over previous
#include <cuda_runtime.h>
#include <cuda_bf16.h>
#include <cstdint>

#define B_   2
#define T_   2048
#define C_   768
#define H_   12
#define DH_  64
#define M_   (B_ * T_)        // 4096 token rows
#define N3C_ (3 * C_)         // 2304

// ---------------------------------------------------------------------------
// Scratch (allocation-free rule: device globals) — all split hi/lo bf16
// ---------------------------------------------------------------------------
__device__ __nv_bfloat16 g_xh[M_ * C_],     g_xl[M_ * C_];      // x split
__device__ __nv_bfloat16 g_wqT_h[N3C_ * C_], g_wqT_l[N3C_ * C_]; // Wqkv^T split
__device__ __nv_bfloat16 g_woT_h[C_ * C_],  g_woT_l[C_ * C_];   // Wout^T split
__device__ __nv_bfloat16 g_qkvh[M_ * N3C_], g_qkvl[M_ * N3C_];  // qkv split
__device__ __nv_bfloat16 g_atth[M_ * C_],   g_attl[M_ * C_];    // att out split

// ---------------------------------------------------------------------------
// Helpers
// ---------------------------------------------------------------------------
__device__ __forceinline__ void split2(float x, float y, uint32_t& hi, uint32_t& lo)
{
    __nv_bfloat16 hx = __float2bfloat16_rn(x);
    __nv_bfloat16 hy = __float2bfloat16_rn(y);
    float rx = x - __bfloat162float(hx);
    float ry = y - __bfloat162float(hy);
    __nv_bfloat162 H; H.x = hx; H.y = hy;
    __nv_bfloat162 L = __floats2bfloat162_rn(rx, ry);
    hi = *reinterpret_cast<uint32_t*>(&H);
    lo = *reinterpret_cast<uint32_t*>(&L);
}

__device__ __forceinline__ void lm4(uint32_t* r, uint32_t addr)
{
    asm volatile("ldmatrix.sync.aligned.m8n8.x4.shared.b16 {%0,%1,%2,%3}, [%4];"
                 : "=r"(r[0]), "=r"(r[1]), "=r"(r[2]), "=r"(r[3]) : "r"(addr));
}

__device__ __forceinline__ void lm4t(uint32_t* r, uint32_t addr)
{
    asm volatile("ldmatrix.sync.aligned.m8n8.x4.trans.shared.b16 {%0,%1,%2,%3}, [%4];"
                 : "=r"(r[0]), "=r"(r[1]), "=r"(r[2]), "=r"(r[3]) : "r"(addr));
}

__device__ __forceinline__ void mma16816(float* d, const uint32_t* a,
                                         uint32_t b0, uint32_t b1)
{
    asm volatile("mma.sync.aligned.m16n8k16.row.col.f32.bf16.bf16.f32 "
                 "{%0,%1,%2,%3}, {%4,%5,%6,%7}, {%8,%9}, {%0,%1,%2,%3};"
                 : "+f"(d[0]), "+f"(d[1]), "+f"(d[2]), "+f"(d[3])
                 : "r"(a[0]), "r"(a[1]), "r"(a[2]), "r"(a[3]), "r"(b0), "r"(b1));
}

__device__ __forceinline__ void cpa16(uint32_t dst, const void* src)
{
    asm volatile("cp.async.cg.shared.global [%0], [%1], 16;" :: "r"(dst), "l"(src));
}
__device__ __forceinline__ void cp_commit()
{
    asm volatile("cp.async.commit_group;");
}
__device__ __forceinline__ void cp_wait0()
{
    asm volatile("cp.async.wait_group 0;");
}
__device__ __forceinline__ void cp_wait1()
{
    asm volatile("cp.async.wait_group 1;");
}

// ---------------------------------------------------------------------------
// One-shot converters
// ---------------------------------------------------------------------------
__global__ void split_flat_kernel(const float* __restrict__ src,
                                  __nv_bfloat16* __restrict__ hi,
                                  __nv_bfloat16* __restrict__ lo, int n4)
{
    int i = blockIdx.x * blockDim.x + threadIdx.x;
    if (i >= n4) return;
    float4 v = ((const float4*)src)[i];
    uint32_t h0, l0, h1, l1;
    split2(v.x, v.y, h0, l0);
    split2(v.z, v.w, h1, l1);
    ((uint2*)hi)[i] = make_uint2(h0, h1);
    ((uint2*)lo)[i] = make_uint2(l0, l1);
}

// src [R][N] fp32 -> dst [N][R] hi/lo bf16  (R,N multiples of 32)
__global__ void splitT_kernel(const float* __restrict__ src,
                              __nv_bfloat16* __restrict__ hiT,
                              __nv_bfloat16* __restrict__ loT,
                              int R, int N)
{
    __shared__ float t[32][33];
    const int c0 = blockIdx.x * 32, r0 = blockIdx.y * 32;
    const int tx = threadIdx.x, ty = threadIdx.y;   // (32,8)
    #pragma unroll
    for (int j = 0; j < 4; j++)
        t[ty + j * 8][tx] = src[(size_t)(r0 + ty + j * 8) * N + c0 + tx];
    __syncthreads();
    #pragma unroll
    for (int j = 0; j < 4; j++) {
        float v = t[tx][ty + j * 8];
        __nv_bfloat16 h = __float2bfloat16_rn(v);
        float r = v - __bfloat162float(h);
        size_t o = (size_t)(c0 + ty + j * 8) * R + r0 + tx;
        hiT[o] = h;
        loT[o] = __float2bfloat16_rn(r);
    }
}

// ---------------------------------------------------------------------------
// Pre-split bf16 GEMM: C[M,N] = (Ah+Al)[M,K] @ (Bh+Bl)^T  (B given as [N][K]).
// Block tile 64x128, warp tile 32x32 (acc=32 regs), BK=64,
// 2-stage cp.async pipeline, 96KB smem -> 2 CTAs/SM without spills.
// Stage layout: Ah@0 (8KB) Al@8K Bh@16K (16KB) Bl@32K ; stage = 48KB.
// ---------------------------------------------------------------------------
#define GEMM_STAGE 49152
#define GEMM_SMEM  (2 * GEMM_STAGE)

template<bool SPLIT_OUT>
__global__ __launch_bounds__(256, 2)
void gemm_pre_kernel(const __nv_bfloat16* __restrict__ Ah,
                     const __nv_bfloat16* __restrict__ Al,
                     const __nv_bfloat16* __restrict__ Bh,
                     const __nv_bfloat16* __restrict__ Bl,
                     float* __restrict__ C,
                     __nv_bfloat16* __restrict__ Ch,
                     __nv_bfloat16* __restrict__ Cl,
                     int M, int N, int K)
{
    extern __shared__ uint8_t smraw[];
    const uint32_t sb = (uint32_t)__cvta_generic_to_shared(smraw);

    const int tid  = threadIdx.x;
    const int lane = tid & 31;
    const int warp = tid >> 5;
    const int wr   = warp >> 2;      // 0..1  (rows)
    const int wc   = warp & 3;       // 0..3  (cols)
    const int row0 = blockIdx.y * 64;
    const int col0 = blockIdx.x * 128;

    const int l7    = lane & 7;
    const int a_row = wr * 32 + (lane & 15);            // + mt*16
    const int a_chi = lane >> 4;
    const int b_n   = wc * 32 + ((lane >> 4) << 3) + l7; // + np*16
    const int b_ckb = (lane >> 3) & 1;

    // loader coords (idx = tid + i*256 -> m = idx>>3, ch = idx&7)
    float acc[2][4][4];
    #pragma unroll
    for (int i = 0; i < 2; i++)
        #pragma unroll
        for (int j = 0; j < 4; j++)
            #pragma unroll
            for (int r = 0; r < 4; r++) acc[i][j][r] = 0.f;

    const int nk = K >> 6;   // K/64

    auto issue = [&](int s, int k0) {
        uint32_t base = sb + s * GEMM_STAGE;
        // A: 64 rows x 8 chunks = 512 cpa16 per array -> 2 per thread
        #pragma unroll
        for (int i = 0; i < 2; i++) {
            int idx = tid + i * 256;
            int m = idx >> 3, ch = idx & 7;
            uint32_t sw = m * 128 + ((uint32_t)(ch ^ (m & 7)) << 4);
            const size_t ga = (size_t)(row0 + m) * K + k0 + ch * 8;
            cpa16(base + sw,        Ah + ga);
            cpa16(base + 8192 + sw, Al + ga);
        }
        // B: 128 rows x 8 chunks = 1024 cpa16 per array -> 4 per thread
        #pragma unroll
        for (int i = 0; i < 4; i++) {
            int idx = tid + i * 256;
            int m = idx >> 3, ch = idx & 7;
            uint32_t sw = m * 128 + ((uint32_t)(ch ^ (m & 7)) << 4);
            const size_t gb = (size_t)(col0 + m) * K + k0 + ch * 8;
            cpa16(base + 16384 + sw, Bh + gb);
            cpa16(base + 32768 + sw, Bl + gb);
        }
    };

    issue(0, 0);
    cp_commit();

    for (int k = 0; k < nk; k++) {
        if (k + 1 < nk) {
            issue((k + 1) & 1, (k + 1) * 64);
            cp_commit();
            cp_wait1();          // stage k complete
        } else {
            cp_wait0();
        }
        __syncthreads();

        const uint32_t st = sb + (k & 1) * GEMM_STAGE;
        #pragma unroll
        for (int kk = 0; kk < 4; kk++) {
            uint32_t bh[8], bl[8];
            #pragma unroll
            for (int np = 0; np < 2; np++) {
                int n = b_n + np * 16;
                uint32_t boff = n * 128 + (((2 * kk + b_ckb) ^ (n & 7)) << 4);
                lm4(&bh[np * 4], st + 16384 + boff);
                lm4(&bl[np * 4], st + 32768 + boff);
            }
            #pragma unroll
            for (int mt = 0; mt < 2; mt++) {
                int row = a_row + mt * 16;
                uint32_t aoff = row * 128 + (((2 * kk + a_chi) ^ (row & 7)) << 4);
                uint32_t ah[4], al[4];
                lm4(ah, st + aoff);
                lm4(al, st + 8192 + aoff);
                #pragma unroll
                for (int nt = 0; nt < 4; nt++) {
                    int bi = (nt >> 1) * 4 + (nt & 1) * 2;
                    mma16816(acc[mt][nt], ah, bh[bi], bh[bi + 1]);
                    mma16816(acc[mt][nt], ah, bl[bi], bl[bi + 1]);
                    mma16816(acc[mt][nt], al, bh[bi], bh[bi + 1]);
                }
            }
        }
        __syncthreads();   // all reads done before stage reuse
    }

    const int g  = lane >> 2;
    const int tg = lane & 3;
    #pragma unroll
    for (int mt = 0; mt < 2; mt++) {
        #pragma unroll
        for (int nt = 0; nt < 4; nt++) {
            int r = row0 + wr * 32 + mt * 16 + g;
            int c = col0 + wc * 32 + nt * 8 + tg * 2;
            if (SPLIT_OUT) {
                uint32_t hh, ll;
                split2(acc[mt][nt][0], acc[mt][nt][1], hh, ll);
                *(uint32_t*)&Ch[(size_t)r * N + c] = hh;
                *(uint32_t*)&Cl[(size_t)r * N + c] = ll;
                split2(acc[mt][nt][2], acc[mt][nt][3], hh, ll);
                *(uint32_t*)&Ch[(size_t)(r + 8) * N + c] = hh;
                *(uint32_t*)&Cl[(size_t)(r + 8) * N + c] = ll;
            } else {
                *(float2*)&C[(size_t)r * N + c] =
                    make_float2(acc[mt][nt][0], acc[mt][nt][1]);
                *(float2*)&C[(size_t)(r + 8) * N + c] =
                    make_float2(acc[mt][nt][2], acc[mt][nt][3]);
            }
        }
    }
}

// ---------------------------------------------------------------------------
// Tensor-core flash attention (causal), split-bf16, pre-split inputs.
// EXACT round-11 version (Q-hoist reverted — it cost registers/occupancy).
// Block: 128 Q-rows x 64 K-cols, 8 warps. cp.async double-buffered K/V.
// Smem 96KB: Qh@0 Ql@16K (128x64); KV buf0@32K, buf1@64K
//            (each: Kh +0, Kl +8K, Vh +16K, Vl +24K; 64x64 tiles).
// ---------------------------------------------------------------------------
#define FBM 128
#define FBN 64
#define FLASH_TC_SMEM (96 * 1024)

__global__ __launch_bounds__(256)
void flash_tc_kernel()
{
    extern __shared__ uint8_t fsm[];
    const uint32_t sb  = (uint32_t)__cvta_generic_to_shared(fsm);
    const uint32_t sQhi = sb;
    const uint32_t sQlo = sb + 16384;

    const int tid  = threadIdx.x;
    const int lane = tid & 31;
    const int w    = tid >> 5;
    const int g    = lane >> 2;
    const int tg   = lane & 3;
    const int bh   = blockIdx.y;
    const int b    = bh / H_;
    const int h    = bh % H_;
    const int qt   = (T_ / FBM - 1) - blockIdx.x;   // heavy q-blocks first
    const int q0   = qt * FBM;
    const long rowbase = (long)b * T_;
    const int qoff = h * DH_;
    const int koff = C_ + h * DH_;
    const int voff = 2 * C_ + h * DH_;
    const float scale = 0.125f;

    auto issueKV = [&](int buf, int k0) {
        const uint32_t kvb = sb + 32768 + buf * 32768;
        #pragma unroll
        for (int i = 0; i < 8; i++) {
            int idx   = tid + i * 256;
            int tsel  = idx >> 9;            // 0:Kh 1:Kl 2:Vh 3:Vl
            int local = idx & 511;
            int m = local >> 3, ch = local & 7;
            const __nv_bfloat16* src = (tsel & 1) ? g_qkvl : g_qkvh;
            int off_ = (tsel < 2) ? koff : voff;
            cpa16(kvb + tsel * 8192 + m * 128 + (((ch ^ (m & 7))) << 4),
                  &src[(rowbase + k0 + m) * (size_t)N3C_ + off_ + ch * 8]);
        }
    };

    // ---- load Q tile [128][64] hi/lo into smem (swizzled) ----
    #pragma unroll
    for (int i = 0; i < 8; i++) {
        int idx   = tid + i * 256;
        int tsel  = idx >> 10;            // 0=hi, 1=lo
        int local = idx & 1023;
        int m = local >> 3, ch = local & 7;
        const __nv_bfloat16* src = tsel ? g_qkvl : g_qkvh;
        uint4 v = *(const uint4*)&src[(rowbase + q0 + m) * (size_t)N3C_ + qoff + ch * 8];
        *(uint4*)(fsm + tsel * 16384 + m * 128 + (((ch ^ (m & 7))) << 4)) = v;
    }

    issueKV(0, 0);
    cp_commit();

    float sacc[8][4], oacc[8][4];
    float mr[2] = {-1e30f, -1e30f};
    float lr[2] = {0.f, 0.f};
    #pragma unroll
    for (int nt = 0; nt < 8; nt++)
        #pragma unroll
        for (int r = 0; r < 4; r++) oacc[nt][r] = 0.f;

    const int wrow0 = q0 + w * 16;
    const int nkt   = (q0 + FBM) / FBN;

    for (int kt = 0; kt < nkt; kt++) {
        const int k0 = kt * FBN;
        const int cur = kt & 1;
        const bool more = (kt + 1 < nkt);

        if (more) { issueKV(cur ^ 1, k0 + FBN); cp_commit(); }
        if (more) cp_wait1(); else cp_wait0();
        __syncthreads();

        const uint32_t sKhi = sb + 32768 + cur * 32768;
        const uint32_t sKlo = sKhi + 8192;
        const uint32_t sVhi = sKhi + 16384;
        const uint32_t sVlo = sKhi + 24576;

        if (k0 <= wrow0 + 15) {
            // ---- S = Q @ K^T ----
            #pragma unroll
            for (int nt = 0; nt < 8; nt++)
                #pragma unroll
                for (int r = 0; r < 4; r++) sacc[nt][r] = 0.f;

            const int arow = w * 16 + (lane & 15);
            #pragma unroll
            for (int kk = 0; kk < 4; kk++) {
                uint32_t ah[4], al[4];
                uint32_t aoff = arow * 128 + (((2 * kk + (lane >> 4)) ^ (arow & 7)) << 4);
                lm4(ah, sQhi + aoff);
                lm4(al, sQlo + aoff);
                #pragma unroll
                for (int ng = 0; ng < 4; ng++) {
                    int n = ng * 16 + ((lane >> 4) << 3) + (lane & 7);
                    uint32_t boff = n * 128 +
                        (((2 * kk + ((lane >> 3) & 1)) ^ (n & 7)) << 4);
                    uint32_t bhv[4], blv[4];
                    lm4(bhv, sKhi + boff);
                    lm4(blv, sKlo + boff);
                    mma16816(sacc[2 * ng],     ah, bhv[0], bhv[1]);
                    mma16816(sacc[2 * ng + 1], ah, bhv[2], bhv[3]);
                    mma16816(sacc[2 * ng],     ah, blv[0], blv[1]);
                    mma16816(sacc[2 * ng + 1], ah, blv[2], blv[3]);
                    mma16816(sacc[2 * ng],     al, bhv[0], bhv[1]);
                    mma16816(sacc[2 * ng + 1], al, bhv[2], bhv[3]);
                }
            }

            // ---- scale + causal mask + online softmax ----
            const bool maskt = (k0 + FBN - 1 > wrow0);
            #pragma unroll
            for (int r = 0; r < 2; r++) {
                const int grow_ = wrow0 + g + r * 8;
                float tmax = -1e30f;
                #pragma unroll
                for (int nt = 0; nt < 8; nt++) {
                    float v0 = sacc[nt][r * 2]     * scale;
                    float v1 = sacc[nt][r * 2 + 1] * scale;
                    if (maskt) {
                        int col = k0 + nt * 8 + tg * 2;
                        if (col     > grow_) v0 = -1e30f;
                        if (col + 1 > grow_) v1 = -1e30f;
                    }
                    sacc[nt][r * 2]     = v0;
                    sacc[nt][r * 2 + 1] = v1;
                    tmax = fmaxf(tmax, fmaxf(v0, v1));
                }
                tmax = fmaxf(tmax, __shfl_xor_sync(0xffffffffu, tmax, 1));
                tmax = fmaxf(tmax, __shfl_xor_sync(0xffffffffu, tmax, 2));
                float newm  = fmaxf(mr[r], tmax);
                float alpha = __expf(mr[r] - newm);
                float sum = 0.f;
                #pragma unroll
                for (int nt = 0; nt < 8; nt++) {
                    float e0 = __expf(sacc[nt][r * 2]     - newm);
                    float e1 = __expf(sacc[nt][r * 2 + 1] - newm);
                    sacc[nt][r * 2]     = e0;
                    sacc[nt][r * 2 + 1] = e1;
                    sum += e0 + e1;
                }
                sum += __shfl_xor_sync(0xffffffffu, sum, 1);
                sum += __shfl_xor_sync(0xffffffffu, sum, 2);
                lr[r] = lr[r] * alpha + sum;
                mr[r] = newm;
                #pragma unroll
                for (int nt = 0; nt < 8; nt++) {
                    oacc[nt][r * 2]     *= alpha;
                    oacc[nt][r * 2 + 1] *= alpha;
                }
            }

            // ---- O += P @ V ----
            #pragma unroll
            for (int ks = 0; ks < 4; ks++) {
                uint32_t pah[4], pal[4];
                split2(sacc[2 * ks][0],     sacc[2 * ks][1],     pah[0], pal[0]);
                split2(sacc[2 * ks][2],     sacc[2 * ks][3],     pah[1], pal[1]);
                split2(sacc[2 * ks + 1][0], sacc[2 * ks + 1][1], pah[2], pal[2]);
                split2(sacc[2 * ks + 1][2], sacc[2 * ks + 1][3], pah[3], pal[3]);
                const int krow = ks * 16 + (lane & 15);
                #pragma unroll
                for (int dg = 0; dg < 4; dg++) {
                    int ch = dg * 2 + (lane >> 4);
                    uint32_t vb = krow * 128 + (((ch ^ (krow & 7))) << 4);
                    uint32_t vh[4], vl[4];
                    lm4t(vh, sVhi + vb);
                    lm4t(vl, sVlo + vb);
                    mma16816(oacc[2 * dg],     pah, vh[0], vh[1]);
                    mma16816(oacc[2 * dg + 1], pah, vh[2], vh[3]);
                    mma16816(oacc[2 * dg],     pah, vl[0], vl[1]);
                    mma16816(oacc[2 * dg + 1], pah, vl[2], vl[3]);
                    mma16816(oacc[2 * dg],     pal, vh[0], vh[1]);
                    mma16816(oacc[2 * dg + 1], pal, vh[2], vh[3]);
                }
            }
        }

        __syncthreads();   // all reads done before next issue overwrites buffer
    }

    // ---- normalize + write split att ----
    const float inv0 = 1.f / lr[0];
    const float inv1 = 1.f / lr[1];
    const long r0 = rowbase + wrow0 + g;
    #pragma unroll
    for (int nt = 0; nt < 8; nt++) {
        int c = qoff + nt * 8 + tg * 2;
        uint32_t hh, ll;
        split2(oacc[nt][0] * inv0, oacc[nt][1] * inv0, hh, ll);
        *(uint32_t*)&g_atth[r0 * C_ + c] = hh;
        *(uint32_t*)&g_attl[r0 * C_ + c] = ll;
        split2(oacc[nt][2] * inv1, oacc[nt][3] * inv1, hh, ll);
        *(uint32_t*)&g_atth[(r0 + 8) * C_ + c] = hh;
        *(uint32_t*)&g_attl[(r0 + 8) * C_ + c] = ll;
    }
}

// ---------------------------------------------------------------------------
extern "C" void kernel_launch(void* const* d_in, const int* in_sizes, int n_in,
                              void* d_out, int out_size)
{
    const float* x    = (const float*)d_in[0];
    const float* Wqkv = (const float*)d_in[1];
    const float* Wout = (const float*)d_in[2];
    float* out = (float*)d_out;

    __nv_bfloat16 *xh, *xl, *wqh, *wql, *woh, *wol, *qh, *ql, *ath, *atl;
    cudaGetSymbolAddress((void**)&xh,  g_xh);
    cudaGetSymbolAddress((void**)&xl,  g_xl);
    cudaGetSymbolAddress((void**)&wqh, g_wqT_h);
    cudaGetSymbolAddress((void**)&wql, g_wqT_l);
    cudaGetSymbolAddress((void**)&woh, g_woT_h);
    cudaGetSymbolAddress((void**)&wol, g_woT_l);
    cudaGetSymbolAddress((void**)&qh,  g_qkvh);
    cudaGetSymbolAddress((void**)&ql,  g_qkvl);
    cudaGetSymbolAddress((void**)&ath, g_atth);
    cudaGetSymbolAddress((void**)&atl, g_attl);

    cudaFuncSetAttribute(gemm_pre_kernel<true>,
                         cudaFuncAttributeMaxDynamicSharedMemorySize, GEMM_SMEM);
    cudaFuncSetAttribute(gemm_pre_kernel<false>,
                         cudaFuncAttributeMaxDynamicSharedMemorySize, GEMM_SMEM);
    cudaFuncSetAttribute(flash_tc_kernel,
                         cudaFuncAttributeMaxDynamicSharedMemorySize, FLASH_TC_SMEM);

    dim3 blk(256);

    // 0) pre-split inputs
    split_flat_kernel<<<(M_ * C_ / 4 + 255) / 256, 256>>>(x, xh, xl, M_ * C_ / 4);
    splitT_kernel<<<dim3(N3C_ / 32, C_ / 32), dim3(32, 8)>>>(Wqkv, wqh, wql, C_, N3C_);
    splitT_kernel<<<dim3(C_ / 32, C_ / 32),  dim3(32, 8)>>>(Wout, woh, wol, C_, C_);

    // 1) QKV projection -> split qkv   (64x128 tiles: grid 18 x 64)
    gemm_pre_kernel<true><<<dim3(N3C_ / 128, M_ / 64), blk, GEMM_SMEM>>>(
        xh, xl, wqh, wql, nullptr, qh, ql, M_, N3C_, C_);

    // 2) causal flash attention -> split att
    flash_tc_kernel<<<dim3(T_ / FBM, B_ * H_), blk, FLASH_TC_SMEM>>>();

    // 3) output projection -> fp32 out (64x128 tiles: grid 6 x 64)
    gemm_pre_kernel<false><<<dim3(C_ / 128, M_ / 64), blk, GEMM_SMEM>>>(
        ath, atl, woh, wol, out, nullptr, nullptr, M_, C_, C_);
}